// round 4
// baseline (speedup 1.0000x reference)
#include <cuda_runtime.h>
#include <cmath>

// Problem dims
constexpr int B_ = 2;
constexpr int S_ = 2048;
constexpr int D_ = 1024;
constexpr int H_ = 16;
constexpr int DH_ = 64;
constexpr int MLP_ = 4096;
constexpr int MROWS = B_ * S_;   // 4096

// ---------------- scratch (device globals; no allocations allowed) ----------
__device__ float g_xln[(size_t)MROWS * D_];     // LN1 output; reused for LN2 output
__device__ float g_q[(size_t)MROWS * D_];       // phi(q)
__device__ float g_k[(size_t)MROWS * D_];       // phi(k)
__device__ float g_v[(size_t)MROWS * D_];       // v
__device__ float g_attn[(size_t)MROWS * D_];    // attention output [bs, h*DH+d]
__device__ float g_xres[(size_t)MROWS * D_];    // attn_out + inputs
__device__ float g_h1[(size_t)MROWS * MLP_];    // MLP hidden

// ---------------- LayerNorm: one block per row of 1024 ----------------------
__global__ void __launch_bounds__(256) ln_kernel(const float* __restrict__ x,
                                                 const float* __restrict__ sc,
                                                 const float* __restrict__ bi,
                                                 float* __restrict__ out) {
    int row = blockIdx.x;
    int tid = threadIdx.x;
    const float4* xr = (const float4*)(x + (size_t)row * D_);
    float4 v = xr[tid];
    float s  = v.x + v.y + v.z + v.w;
    float s2 = v.x * v.x + v.y * v.y + v.z * v.z + v.w * v.w;
    #pragma unroll
    for (int o = 16; o > 0; o >>= 1) {
        s  += __shfl_xor_sync(0xffffffffu, s, o);
        s2 += __shfl_xor_sync(0xffffffffu, s2, o);
    }
    __shared__ float rs[8], rs2[8];
    int w = tid >> 5, lane = tid & 31;
    if (lane == 0) { rs[w] = s; rs2[w] = s2; }
    __syncthreads();
    if (tid == 0) {
        float a = 0.f, b = 0.f;
        #pragma unroll
        for (int i = 0; i < 8; i++) { a += rs[i]; b += rs2[i]; }
        rs[0] = a; rs2[0] = b;
    }
    __syncthreads();
    s = rs[0]; s2 = rs2[0];
    float mean = s * (1.0f / D_);
    float var  = s2 * (1.0f / D_) - mean * mean;
    float inv  = rsqrtf(var + 1e-6f);
    float4 sc4 = ((const float4*)sc)[tid];
    float4 bi4 = ((const float4*)bi)[tid];
    float4 o4;
    o4.x = (v.x - mean) * inv * sc4.x + bi4.x;
    o4.y = (v.y - mean) * inv * sc4.y + bi4.y;
    o4.z = (v.z - mean) * inv * sc4.z + bi4.z;
    o4.w = (v.w - mean) * inv * sc4.w + bi4.w;
    ((float4*)(out + (size_t)row * D_))[tid] = o4;
}

// ---------------- SGEMM 128x128x16, 8x8 per thread, fused epilogues ---------
enum { EPI_NONE = 0, EPI_PHI = 1, EPI_BIAS_GELU = 2, EPI_ADD = 3, EPI_BIAS_ADD = 4 };

__device__ __forceinline__ float gelu_tanh(float x) {
    float x3 = x * x * x;
    return 0.5f * x * (1.0f + tanhf(0.7978845608028654f * (x + 0.044715f * x3)));
}

template <int EPI>
__global__ void __launch_bounds__(256, 2)
sgemm_kernel(const float* __restrict__ A, const float* __restrict__ Bm,
             float* __restrict__ C, int M, int N, int K,
             const float* __restrict__ bias, const float* __restrict__ add) {
    constexpr int BM = 128, BN = 128, BK = 16;
    __shared__ float As[BK][BM];
    __shared__ float Bs[BK][BN];
    int tid = threadIdx.x;
    int n0 = blockIdx.x * BN;
    int m0 = blockIdx.y * BM;
    int tx = tid & 15;   // output col group
    int ty = tid >> 4;   // output row group
    float acc[8][8];
    #pragma unroll
    for (int i = 0; i < 8; i++)
        #pragma unroll
        for (int j = 0; j < 8; j++) acc[i][j] = 0.f;

    int arow = tid >> 2;          // 0..63
    int acol = (tid & 3) * 4;     // 0,4,8,12
    int brow = tid >> 5;          // 0..7
    int bcol = (tid & 31) * 4;    // 0..124

    const float* Aptr = A + (size_t)(m0 + arow) * K + acol;
    const float* Bptr = Bm + (size_t)brow * N + (n0 + bcol);

    for (int kt = 0; kt < K; kt += BK) {
        float4 a0 = *(const float4*)(Aptr);
        float4 a1 = *(const float4*)(Aptr + (size_t)64 * K);
        float4 b0 = *(const float4*)(Bptr);
        float4 b1 = *(const float4*)(Bptr + (size_t)8 * N);
        Aptr += BK;
        Bptr += (size_t)BK * N;

        As[acol + 0][arow] = a0.x; As[acol + 1][arow] = a0.y;
        As[acol + 2][arow] = a0.z; As[acol + 3][arow] = a0.w;
        As[acol + 0][64 + arow] = a1.x; As[acol + 1][64 + arow] = a1.y;
        As[acol + 2][64 + arow] = a1.z; As[acol + 3][64 + arow] = a1.w;
        *(float4*)&Bs[brow][bcol]     = b0;
        *(float4*)&Bs[brow + 8][bcol] = b1;
        __syncthreads();

        #pragma unroll
        for (int kk = 0; kk < BK; kk++) {
            float ar[8], br[8];
            *(float4*)&ar[0] = *(const float4*)&As[kk][ty * 8];
            *(float4*)&ar[4] = *(const float4*)&As[kk][ty * 8 + 4];
            *(float4*)&br[0] = *(const float4*)&Bs[kk][tx * 8];
            *(float4*)&br[4] = *(const float4*)&Bs[kk][tx * 8 + 4];
            #pragma unroll
            for (int i = 0; i < 8; i++)
                #pragma unroll
                for (int j = 0; j < 8; j++)
                    acc[i][j] = fmaf(ar[i], br[j], acc[i][j]);
        }
        __syncthreads();
    }

    // epilogue
    #pragma unroll
    for (int i = 0; i < 8; i++) {
        size_t row = (size_t)(m0 + ty * 8 + i);
        int ncol = n0 + tx * 8;
        float* crow = C + row * N + ncol;
        #pragma unroll
        for (int jj = 0; jj < 8; jj += 4) {
            float4 r;
            float vv[4];
            #pragma unroll
            for (int q = 0; q < 4; q++) vv[q] = acc[i][jj + q];
            if (EPI == EPI_PHI) {
                #pragma unroll
                for (int q = 0; q < 4; q++) vv[q] = fmaxf(vv[q], 0.f) + 1e-3f;
            } else if (EPI == EPI_BIAS_GELU) {
                float4 b4 = *(const float4*)(bias + ncol + jj);
                vv[0] = gelu_tanh(vv[0] + b4.x);
                vv[1] = gelu_tanh(vv[1] + b4.y);
                vv[2] = gelu_tanh(vv[2] + b4.z);
                vv[3] = gelu_tanh(vv[3] + b4.w);
            } else if (EPI == EPI_ADD) {
                float4 a4 = *(const float4*)(add + row * N + ncol + jj);
                vv[0] += a4.x; vv[1] += a4.y; vv[2] += a4.z; vv[3] += a4.w;
            } else if (EPI == EPI_BIAS_ADD) {
                float4 b4 = *(const float4*)(bias + ncol + jj);
                float4 a4 = *(const float4*)(add + row * N + ncol + jj);
                vv[0] += b4.x + a4.x; vv[1] += b4.y + a4.y;
                vv[2] += b4.z + a4.z; vv[3] += b4.w + a4.w;
            }
            r.x = vv[0]; r.y = vv[1]; r.z = vv[2]; r.w = vv[3];
            *(float4*)(crow + jj) = r;
        }
    }
}

// ---------------- Performer causal scan: one block per (b,h) ----------------
// State: kv[64][64] + ksum[64] per (b,h). 256 threads: thread owns column d
// (tid&63) and m-quarter (tid>>6) of 16 rows. num reduced over 4 quarters via
// shared; den maintained by the d==0 thread of each quarter.
__global__ void __launch_bounds__(256, 1)
attn_scan_kernel(const float* __restrict__ phiq, const float* __restrict__ phik,
                 const float* __restrict__ v, float* __restrict__ out) {
    constexpr int T = 16;
    __shared__ float sk[T][64];
    __shared__ float sq[T][64];
    __shared__ float sv[T][64];
    __shared__ float partNum[4][64];
    __shared__ float partDen[4];

    int bh = blockIdx.x;                    // 0..31
    const size_t base = (size_t)(bh >> 4) * S_ * D_ + (size_t)(bh & 15) * DH_;
    int tid = threadIdx.x;
    int d  = tid & 63;
    int qm = tid >> 6;      // 0..3
    int m0 = qm * 16;

    float kv[16], ksum[16];
    #pragma unroll
    for (int i = 0; i < 16; i++) { kv[i] = 0.f; ksum[i] = 0.f; }

    int lt = tid >> 4;          // token-in-chunk 0..15
    int lf = (tid & 15) * 4;    // float4 offset within 64

    for (int c0 = 0; c0 < S_; c0 += T) {
        __syncthreads();
        size_t g = base + (size_t)(c0 + lt) * D_ + lf;
        *(float4*)&sk[lt][lf] = *(const float4*)(phik + g);
        *(float4*)&sq[lt][lf] = *(const float4*)(phiq + g);
        *(float4*)&sv[lt][lf] = *(const float4*)(v + g);
        __syncthreads();

        for (int t = 0; t < T; t++) {
            float vd = sv[t][d];
            float pk[16], pq[16];
            #pragma unroll
            for (int i = 0; i < 16; i += 4) {
                *(float4*)&pk[i] = *(const float4*)&sk[t][m0 + i];
                *(float4*)&pq[i] = *(const float4*)&sq[t][m0 + i];
            }
            float np = 0.f;
            #pragma unroll
            for (int i = 0; i < 16; i++) {
                kv[i] = fmaf(pk[i], vd, kv[i]);
                np = fmaf(pq[i], kv[i], np);
            }
            if (d == 0) {
                float dp = 0.f;
                #pragma unroll
                for (int i = 0; i < 16; i++) {
                    ksum[i] += pk[i];
                    dp = fmaf(pq[i], ksum[i], dp);
                }
                partDen[qm] = dp;
            }
            partNum[qm][d] = np;
            __syncthreads();
            if (tid < 64) {
                float num = partNum[0][tid] + partNum[1][tid] +
                            partNum[2][tid] + partNum[3][tid];
                float den = partDen[0] + partDen[1] + partDen[2] + partDen[3];
                out[base + (size_t)(c0 + t) * D_ + tid] = num / den;
            }
            __syncthreads();
        }
    }
}

// ---------------- launcher ---------------------------------------------------
extern "C" void kernel_launch(void* const* d_in, const int* in_sizes, int n_in,
                              void* d_out, int out_size) {
    (void)in_sizes; (void)n_in; (void)out_size;
    const float* inputs    = (const float*)d_in[0];
    const float* ln1_scale = (const float*)d_in[1];
    const float* ln1_bias  = (const float*)d_in[2];
    const float* wq        = (const float*)d_in[3];   // [D, H*DH]
    const float* wk        = (const float*)d_in[4];
    const float* wv        = (const float*)d_in[5];
    const float* wo        = (const float*)d_in[6];   // [H*DH, D]
    const float* ln2_scale = (const float*)d_in[7];
    const float* ln2_bias  = (const float*)d_in[8];
    const float* w1        = (const float*)d_in[9];   // [D, MLP]
    const float* b1        = (const float*)d_in[10];
    const float* w2        = (const float*)d_in[11];  // [MLP, D]
    const float* b2        = (const float*)d_in[12];
    float* out = (float*)d_out;

    float *xln, *q, *k, *v, *attn, *xres, *h1;
    cudaGetSymbolAddress((void**)&xln,  g_xln);
    cudaGetSymbolAddress((void**)&q,    g_q);
    cudaGetSymbolAddress((void**)&k,    g_k);
    cudaGetSymbolAddress((void**)&v,    g_v);
    cudaGetSymbolAddress((void**)&attn, g_attn);
    cudaGetSymbolAddress((void**)&xres, g_xres);
    cudaGetSymbolAddress((void**)&h1,   g_h1);

    // 1. LN1
    ln_kernel<<<MROWS, 256>>>(inputs, ln1_scale, ln1_bias, xln);

    // 2-4. QKV projections with fused phi (relu+eps) on q,k
    dim3 gq(D_ / 128, MROWS / 128);   // (8, 32)
    sgemm_kernel<EPI_PHI><<<gq, 256>>>(xln, wq, q, MROWS, D_, D_, nullptr, nullptr);
    sgemm_kernel<EPI_PHI><<<gq, 256>>>(xln, wk, k, MROWS, D_, D_, nullptr, nullptr);
    sgemm_kernel<EPI_NONE><<<gq, 256>>>(xln, wv, v, MROWS, D_, D_, nullptr, nullptr);

    // 5. Performer causal scan
    attn_scan_kernel<<<B_ * H_, 256>>>(q, k, v, attn);

    // 6. Output projection + residual
    sgemm_kernel<EPI_ADD><<<gq, 256>>>(attn, wo, xres, MROWS, D_, D_, nullptr, inputs);

    // 7. LN2 (reuse xln as y)
    ln_kernel<<<MROWS, 256>>>(xres, ln2_scale, ln2_bias, xln);

    // 8. MLP up + bias + gelu
    dim3 g1(MLP_ / 128, MROWS / 128); // (32, 32)
    sgemm_kernel<EPI_BIAS_GELU><<<g1, 256>>>(xln, w1, h1, MROWS, MLP_, D_, b1, nullptr);

    // 9. MLP down + bias + residual -> out
    dim3 g2(D_ / 128, MROWS / 128);   // (8, 32)
    sgemm_kernel<EPI_BIAS_ADD><<<g2, 256>>>(h1, w2, out, MROWS, D_, MLP_, b2, xres);
}

// round 6
// speedup vs baseline: 1.5502x; 1.5502x over previous
#include <cuda_runtime.h>
#include <cstdint>
#include <cmath>

// Problem dims
constexpr int B_ = 2;
constexpr int S_ = 2048;
constexpr int D_ = 1024;
constexpr int H_ = 16;
constexpr int DH_ = 64;
constexpr int MLP_ = 4096;
constexpr int MROWS = B_ * S_;   // 4096

// ---------------- scratch (device globals; no allocations allowed) ----------
__device__ float g_xln[(size_t)MROWS * D_];
__device__ float g_q[(size_t)MROWS * D_];
__device__ float g_k[(size_t)MROWS * D_];
__device__ float g_v[(size_t)MROWS * D_];
__device__ float g_attn[(size_t)MROWS * D_];
__device__ float g_xres[(size_t)MROWS * D_];
__device__ float g_h1[(size_t)MROWS * MLP_];

// ======================= LayerNorm ==========================================
__global__ void __launch_bounds__(256) ln_kernel(const float* __restrict__ x,
                                                 const float* __restrict__ sc,
                                                 const float* __restrict__ bi,
                                                 float* __restrict__ out) {
    int row = blockIdx.x;
    int tid = threadIdx.x;
    const float4* xr = (const float4*)(x + (size_t)row * D_);
    float4 v = xr[tid];
    float s  = v.x + v.y + v.z + v.w;
    float s2 = v.x * v.x + v.y * v.y + v.z * v.z + v.w * v.w;
    #pragma unroll
    for (int o = 16; o > 0; o >>= 1) {
        s  += __shfl_xor_sync(0xffffffffu, s, o);
        s2 += __shfl_xor_sync(0xffffffffu, s2, o);
    }
    __shared__ float rs[8], rs2[8];
    int w = tid >> 5, lane = tid & 31;
    if (lane == 0) { rs[w] = s; rs2[w] = s2; }
    __syncthreads();
    if (tid == 0) {
        float a = 0.f, b = 0.f;
        #pragma unroll
        for (int i = 0; i < 8; i++) { a += rs[i]; b += rs2[i]; }
        rs[0] = a; rs2[0] = b;
    }
    __syncthreads();
    s = rs[0]; s2 = rs2[0];
    float mean = s * (1.0f / D_);
    float var  = s2 * (1.0f / D_) - mean * mean;
    float inv  = rsqrtf(var + 1e-6f);
    float4 sc4 = ((const float4*)sc)[tid];
    float4 bi4 = ((const float4*)bi)[tid];
    float4 o4;
    o4.x = (v.x - mean) * inv * sc4.x + bi4.x;
    o4.y = (v.y - mean) * inv * sc4.y + bi4.y;
    o4.z = (v.z - mean) * inv * sc4.z + bi4.z;
    o4.w = (v.w - mean) * inv * sc4.w + bi4.w;
    ((float4*)(out + (size_t)row * D_))[tid] = o4;
}

// ======================= tf32 mma.sync GEMM =================================
enum { EPI_NONE = 0, EPI_PHI = 1, EPI_BIAS_GELU = 2, EPI_ADD = 3, EPI_BIAS_ADD = 4 };

__device__ __forceinline__ float gelu_tanh(float x) {
    float x3 = x * x * x;
    return 0.5f * x * (1.0f + tanhf(0.7978845608028654f * (x + 0.044715f * x3)));
}
__device__ __forceinline__ uint32_t f2tf(float f) {
    uint32_t u;
    asm("cvt.rna.tf32.f32 %0, %1;" : "=r"(u) : "f"(f));
    return u;
}
__device__ __forceinline__ void mma_tf32(float* d, uint32_t a0, uint32_t a1,
                                         uint32_t a2, uint32_t a3,
                                         uint32_t b0, uint32_t b1) {
    asm volatile(
        "mma.sync.aligned.m16n8k8.row.col.f32.tf32.tf32.f32 "
        "{%0,%1,%2,%3}, {%4,%5,%6,%7}, {%8,%9}, {%0,%1,%2,%3};"
        : "+f"(d[0]), "+f"(d[1]), "+f"(d[2]), "+f"(d[3])
        : "r"(a0), "r"(a1), "r"(a2), "r"(a3), "r"(b0), "r"(b1));
}

// SMEM layout (double buffered, padded strides to kill bank conflicts)
constexpr int SA = 36;    // A row stride in floats (128 rows x 32 cols)
constexpr int SB = 132;   // B row stride in floats (32 rows x 128 cols)
constexpr int ABYTES = 128 * SA * 4;          // 18432
constexpr int BBYTES = 32 * SB * 4;           // 16896
constexpr int BUFB   = ABYTES + BBYTES;       // 35328
constexpr int SMEM_GEMM = 2 * BUFB;           // 70656

// C[M,N] = A[M,K] @ B[K,N]; CTA 128x128, BK=32, 8 warps of 64x32.
template <int EPI>
__global__ void __launch_bounds__(256)
mma_gemm(const float* __restrict__ A, const float* __restrict__ Bm,
         float* __restrict__ C, int M, int N, int K,
         const float* __restrict__ bias, const float* __restrict__ add) {
    extern __shared__ char smem[];
    const int tid  = threadIdx.x;
    const int lane = tid & 31;
    const int wid  = tid >> 5;
    const int wm   = wid & 1;          // warp m-half (0/1) -> 64 rows
    const int wn   = wid >> 1;         // warp n-quarter (0..3) -> 32 cols
    const int m0   = blockIdx.y * 128;
    const int n0   = blockIdx.x * 128;
    const int g    = lane >> 2;        // group id 0..7
    const int t    = lane & 3;         // thread-in-group 0..3

    // global load mapping
    const int arow = tid >> 1;                 // 0..127
    const int acb  = (tid & 1) * 16;           // col base 0/16
    const int brow = tid >> 3;                 // 0..31
    const int bcb  = (tid & 7) * 16;           // col base 0..112

    const float* Ap = A + (size_t)(m0 + arow) * K + acb;
    const float* Bp = Bm + (size_t)brow * N + n0 + bcb;

    float acc[4][4][4];
    #pragma unroll
    for (int i = 0; i < 4; i++)
        #pragma unroll
        for (int j = 0; j < 4; j++)
            #pragma unroll
            for (int q = 0; q < 4; q++) acc[i][j][q] = 0.f;

    float4 ra[4], rb[4];
    #pragma unroll
    for (int i = 0; i < 4; i++) {
        ra[i] = *(const float4*)(Ap + 4 * i);
        rb[i] = *(const float4*)(Bp + 4 * i);
    }

    auto storebuf = [&](int p) {
        uint32_t* As = (uint32_t*)(smem + p * BUFB);
        uint32_t* Bs = (uint32_t*)(smem + p * BUFB + ABYTES);
        #pragma unroll
        for (int i = 0; i < 4; i++) {
            uint4 u;
            u.x = f2tf(ra[i].x); u.y = f2tf(ra[i].y);
            u.z = f2tf(ra[i].z); u.w = f2tf(ra[i].w);
            *(uint4*)&As[arow * SA + acb + 4 * i] = u;
        }
        #pragma unroll
        for (int i = 0; i < 4; i++) {
            uint4 u;
            u.x = f2tf(rb[i].x); u.y = f2tf(rb[i].y);
            u.z = f2tf(rb[i].z); u.w = f2tf(rb[i].w);
            *(uint4*)&Bs[brow * SB + bcb + 4 * i] = u;
        }
    };

    storebuf(0);
    const int NT = K >> 5;
    for (int kt = 0; kt < NT; kt++) {
        __syncthreads();
        const int p = kt & 1;
        if (kt + 1 < NT) {
            Ap += 32;
            Bp += (size_t)32 * N;
            #pragma unroll
            for (int i = 0; i < 4; i++) {
                ra[i] = *(const float4*)(Ap + 4 * i);
                rb[i] = *(const float4*)(Bp + 4 * i);
            }
        }
        const uint32_t* As = (const uint32_t*)(smem + p * BUFB);
        const uint32_t* Bs = (const uint32_t*)(smem + p * BUFB + ABYTES);

        #pragma unroll
        for (int kk = 0; kk < 4; kk++) {
            const int kb = kk * 8 + t;
            const int nin = wn * 32 + g;
            uint32_t bf[4][2];
            #pragma unroll
            for (int nj = 0; nj < 4; nj++) {
                bf[nj][0] = Bs[kb * SB + nin + nj * 8];
                bf[nj][1] = Bs[(kb + 4) * SB + nin + nj * 8];
            }
            #pragma unroll
            for (int mi = 0; mi < 4; mi++) {
                const int r = wm * 64 + mi * 16 + g;
                const int c = kk * 8 + t;
                uint32_t a0 = As[r * SA + c];
                uint32_t a1 = As[(r + 8) * SA + c];
                uint32_t a2 = As[r * SA + c + 4];
                uint32_t a3 = As[(r + 8) * SA + c + 4];
                #pragma unroll
                for (int nj = 0; nj < 4; nj++)
                    mma_tf32(acc[mi][nj], a0, a1, a2, a3, bf[nj][0], bf[nj][1]);
            }
        }
        if (kt + 1 < NT) storebuf(1 - p);
    }

    // epilogue: thread owns, per (mi,nj): rows r0,r0+8 ; cols cc,cc+1
    #pragma unroll
    for (int mi = 0; mi < 4; mi++) {
        #pragma unroll
        for (int nj = 0; nj < 4; nj++) {
            const int r0 = m0 + wm * 64 + mi * 16 + g;
            const int cc = n0 + wn * 32 + nj * 8 + 2 * t;
            #pragma unroll
            for (int hh = 0; hh < 2; hh++) {
                const int row = r0 + hh * 8;
                float vx = acc[mi][nj][2 * hh + 0];
                float vy = acc[mi][nj][2 * hh + 1];
                if (EPI == EPI_PHI) {
                    vx = fmaxf(vx, 0.f) + 1e-3f;
                    vy = fmaxf(vy, 0.f) + 1e-3f;
                } else if (EPI == EPI_BIAS_GELU) {
                    float2 b2 = *(const float2*)(bias + cc);
                    vx = gelu_tanh(vx + b2.x);
                    vy = gelu_tanh(vy + b2.y);
                } else if (EPI == EPI_ADD) {
                    float2 a2 = *(const float2*)(add + (size_t)row * N + cc);
                    vx += a2.x; vy += a2.y;
                } else if (EPI == EPI_BIAS_ADD) {
                    float2 b2 = *(const float2*)(bias + cc);
                    float2 a2 = *(const float2*)(add + (size_t)row * N + cc);
                    vx += b2.x + a2.x; vy += b2.y + a2.y;
                }
                float2 r2; r2.x = vx; r2.y = vy;
                *(float2*)(C + (size_t)row * N + cc) = r2;
            }
        }
    }
}

// ======================= Performer causal scan ==============================
__global__ void __launch_bounds__(256, 1)
attn_scan_kernel(const float* __restrict__ phiq, const float* __restrict__ phik,
                 const float* __restrict__ v, float* __restrict__ out) {
    constexpr int T = 16;
    __shared__ float sk[T][64];
    __shared__ float sq[T][64];
    __shared__ float sv[T][64];
    __shared__ float partNum[4][64];
    __shared__ float partDen[4];

    int bh = blockIdx.x;
    const size_t base = (size_t)(bh >> 4) * S_ * D_ + (size_t)(bh & 15) * DH_;
    int tid = threadIdx.x;
    int d  = tid & 63;
    int qm = tid >> 6;
    int m0 = qm * 16;

    float kv[16], ksum[16];
    #pragma unroll
    for (int i = 0; i < 16; i++) { kv[i] = 0.f; ksum[i] = 0.f; }

    int lt = tid >> 4;
    int lf = (tid & 15) * 4;

    for (int c0 = 0; c0 < S_; c0 += T) {
        __syncthreads();
        size_t gg = base + (size_t)(c0 + lt) * D_ + lf;
        *(float4*)&sk[lt][lf] = *(const float4*)(phik + gg);
        *(float4*)&sq[lt][lf] = *(const float4*)(phiq + gg);
        *(float4*)&sv[lt][lf] = *(const float4*)(v + gg);
        __syncthreads();

        for (int tt = 0; tt < T; tt++) {
            float vd = sv[tt][d];
            float pk[16], pq[16];
            #pragma unroll
            for (int i = 0; i < 16; i += 4) {
                *(float4*)&pk[i] = *(const float4*)&sk[tt][m0 + i];
                *(float4*)&pq[i] = *(const float4*)&sq[tt][m0 + i];
            }
            float np = 0.f;
            #pragma unroll
            for (int i = 0; i < 16; i++) {
                kv[i] = fmaf(pk[i], vd, kv[i]);
                np = fmaf(pq[i], kv[i], np);
            }
            if (d == 0) {
                float dp = 0.f;
                #pragma unroll
                for (int i = 0; i < 16; i++) {
                    ksum[i] += pk[i];
                    dp = fmaf(pq[i], ksum[i], dp);
                }
                partDen[qm] = dp;
            }
            partNum[qm][d] = np;
            __syncthreads();
            if (tid < 64) {
                float num = partNum[0][tid] + partNum[1][tid] +
                            partNum[2][tid] + partNum[3][tid];
                float den = partDen[0] + partDen[1] + partDen[2] + partDen[3];
                out[base + (size_t)(c0 + tt) * D_ + tid] = num / den;
            }
            __syncthreads();
        }
    }
}

// ======================= launcher ===========================================
extern "C" void kernel_launch(void* const* d_in, const int* in_sizes, int n_in,
                              void* d_out, int out_size) {
    (void)in_sizes; (void)n_in; (void)out_size;
    const float* inputs    = (const float*)d_in[0];
    const float* ln1_scale = (const float*)d_in[1];
    const float* ln1_bias  = (const float*)d_in[2];
    const float* wq        = (const float*)d_in[3];
    const float* wk        = (const float*)d_in[4];
    const float* wv        = (const float*)d_in[5];
    const float* wo        = (const float*)d_in[6];
    const float* ln2_scale = (const float*)d_in[7];
    const float* ln2_bias  = (const float*)d_in[8];
    const float* w1        = (const float*)d_in[9];
    const float* b1        = (const float*)d_in[10];
    const float* w2        = (const float*)d_in[11];
    const float* b2        = (const float*)d_in[12];
    float* out = (float*)d_out;

    float *xln, *q, *k, *v, *attn, *xres, *h1;
    cudaGetSymbolAddress((void**)&xln,  g_xln);
    cudaGetSymbolAddress((void**)&q,    g_q);
    cudaGetSymbolAddress((void**)&k,    g_k);
    cudaGetSymbolAddress((void**)&v,    g_v);
    cudaGetSymbolAddress((void**)&attn, g_attn);
    cudaGetSymbolAddress((void**)&xres, g_xres);
    cudaGetSymbolAddress((void**)&h1,   g_h1);

    cudaFuncSetAttribute(mma_gemm<EPI_NONE>,      cudaFuncAttributeMaxDynamicSharedMemorySize, SMEM_GEMM);
    cudaFuncSetAttribute(mma_gemm<EPI_PHI>,       cudaFuncAttributeMaxDynamicSharedMemorySize, SMEM_GEMM);
    cudaFuncSetAttribute(mma_gemm<EPI_ADD>,       cudaFuncAttributeMaxDynamicSharedMemorySize, SMEM_GEMM);
    cudaFuncSetAttribute(mma_gemm<EPI_BIAS_GELU>, cudaFuncAttributeMaxDynamicSharedMemorySize, SMEM_GEMM);
    cudaFuncSetAttribute(mma_gemm<EPI_BIAS_ADD>,  cudaFuncAttributeMaxDynamicSharedMemorySize, SMEM_GEMM);

    // 1. LN1
    ln_kernel<<<MROWS, 256>>>(inputs, ln1_scale, ln1_bias, xln);

    // 2-4. QKV projections (fused phi on q,k)
    dim3 gq(D_ / 128, MROWS / 128);
    mma_gemm<EPI_PHI><<<gq, 256, SMEM_GEMM>>>(xln, wq, q, MROWS, D_, D_, nullptr, nullptr);
    mma_gemm<EPI_PHI><<<gq, 256, SMEM_GEMM>>>(xln, wk, k, MROWS, D_, D_, nullptr, nullptr);
    mma_gemm<EPI_NONE><<<gq, 256, SMEM_GEMM>>>(xln, wv, v, MROWS, D_, D_, nullptr, nullptr);

    // 5. Performer causal scan
    attn_scan_kernel<<<B_ * H_, 256>>>(q, k, v, attn);

    // 6. Output projection + residual
    mma_gemm<EPI_ADD><<<gq, 256, SMEM_GEMM>>>(attn, wo, xres, MROWS, D_, D_, nullptr, inputs);

    // 7. LN2
    ln_kernel<<<MROWS, 256>>>(xres, ln2_scale, ln2_bias, xln);

    // 8. MLP up + bias + gelu
    dim3 g1(MLP_ / 128, MROWS / 128);
    mma_gemm<EPI_BIAS_GELU><<<g1, 256, SMEM_GEMM>>>(xln, w1, h1, MROWS, MLP_, D_, b1, nullptr);

    // 9. MLP down + bias + residual -> out
    dim3 g2(D_ / 128, MROWS / 128);
    mma_gemm<EPI_BIAS_ADD><<<g2, 256, SMEM_GEMM>>>(h1, w2, out, MROWS, D_, MLP_, b2, xres);
}